// round 2
// baseline (speedup 1.0000x reference)
#include <cuda_runtime.h>
#include <math.h>

// Problem constants
#define Bc 4
#define Tc 4096
#define Ec 1024
#define Hc 16
#define Sc 64
#define Dc 64
#define Mc (Bc * Tc)   // 16384

// ---------------- scratch (device globals: alloc-free rule) ----------------
__device__ float g_q[(size_t)Mc * Ec];
__device__ float g_k[(size_t)Mc * Ec];
__device__ float g_v[(size_t)Mc * Ec];
__device__ float g_ro[(size_t)Mc * Ec];
__device__ float g_slot[Bc * Hc * Sc * Dc];     // [b][h][s][d]
__device__ float g_cos[Tc * 32];
__device__ float g_sin[Tc * 32];

// ---------------- rope tables: cos/sin(t * invf[i]), i in [0,32) ----------------
__global__ void rope_table_kernel(float* __restrict__ ct, float* __restrict__ st) {
    int t = blockIdx.x;           // 0..4095
    int i = threadIdx.x;          // 0..31
    double p = pow(10000.0, -(double)i / 32.0);
    float invf = (float)p;
    float ang = (float)t * invf;  // matches reference fp32 angle math
    ct[t * 32 + i] = cosf(ang);
    st[t * 32 + i] = sinf(ang);
}

__global__ void zero_kernel(float* __restrict__ p, int n) {
    int i = blockIdx.x * 256 + threadIdx.x;
    if (i < n) p[i] = 0.0f;
}

// ---------------- 128x128x8 fp32 NT GEMM, double-buffered, optional RoPE epilogue ----
// C[m][n] = sum_k A[m][k] * B[n][k];  K = N = 1024, M = 16384.
template <int ROPE>
__global__ __launch_bounds__(256, 2)
void sgemm128(const float* __restrict__ A, const float* __restrict__ B,
              float* __restrict__ C,
              const float* __restrict__ ctab, const float* __restrict__ stab) {
    __shared__ float As[2][8][128];
    __shared__ float Bs[2][8][128];

    const int tid = threadIdx.x;
    const int bn = blockIdx.x;    // n tile (0..7)
    const int bm = blockIdx.y;    // m tile (0..127)

    const int lrow = tid >> 1;          // 0..127 (tile row loaded by this thread)
    const int lk   = (tid & 1) << 2;    // 0 or 4 (k offset)
    const float* Ag = A + (size_t)(bm * 128 + lrow) * 1024 + lk;
    const float* Bg = B + (size_t)(bn * 128 + lrow) * 1024 + lk;

    const int tx = tid & 15;            // n sub-tile
    const int ty = tid >> 4;            // m sub-tile

    float acc[8][8];
#pragma unroll
    for (int i = 0; i < 8; i++)
#pragma unroll
        for (int j = 0; j < 8; j++) acc[i][j] = 0.0f;

    // preload tile 0
    float4 av = *(const float4*)Ag;
    float4 bv = *(const float4*)Bg;
    As[0][lk + 0][lrow] = av.x; As[0][lk + 1][lrow] = av.y;
    As[0][lk + 2][lrow] = av.z; As[0][lk + 3][lrow] = av.w;
    Bs[0][lk + 0][lrow] = bv.x; Bs[0][lk + 1][lrow] = bv.y;
    Bs[0][lk + 2][lrow] = bv.z; Bs[0][lk + 3][lrow] = bv.w;
    __syncthreads();

    int buf = 0;
    for (int kt = 0; kt < 128; kt++) {
        float4 av2, bv2;
        if (kt < 127) {
            av2 = *(const float4*)(Ag + (size_t)(kt + 1) * 8);
            bv2 = *(const float4*)(Bg + (size_t)(kt + 1) * 8);
        }
#pragma unroll
        for (int kk = 0; kk < 8; kk++) {
            float a[8], b[8];
            *(float4*)&a[0] = *(const float4*)&As[buf][kk][ty * 8];
            *(float4*)&a[4] = *(const float4*)&As[buf][kk][ty * 8 + 4];
            *(float4*)&b[0] = *(const float4*)&Bs[buf][kk][tx * 8];
            *(float4*)&b[4] = *(const float4*)&Bs[buf][kk][tx * 8 + 4];
#pragma unroll
            for (int i = 0; i < 8; i++)
#pragma unroll
                for (int j = 0; j < 8; j++) acc[i][j] += a[i] * b[j];
        }
        if (kt < 127) {
            buf ^= 1;
            As[buf][lk + 0][lrow] = av2.x; As[buf][lk + 1][lrow] = av2.y;
            As[buf][lk + 2][lrow] = av2.z; As[buf][lk + 3][lrow] = av2.w;
            Bs[buf][lk + 0][lrow] = bv2.x; Bs[buf][lk + 1][lrow] = bv2.y;
            Bs[buf][lk + 2][lrow] = bv2.z; Bs[buf][lk + 3][lrow] = bv2.w;
            __syncthreads();
        }
    }

    // epilogue (+ optional RoPE; n pairs (even, odd) are adjacent in-register)
    const int nb = bn * 128 + tx * 8;
#pragma unroll
    for (int i = 0; i < 8; i++) {
        int m = bm * 128 + ty * 8 + i;
        int t = m & (Tc - 1);
        float o[8];
        if (ROPE) {
#pragma unroll
            for (int jp = 0; jp < 4; jp++) {
                int j = jp * 2;
                int n0 = nb + j;
                int i0 = n0 & 31;
                int i1 = (n0 + 1) & 31;
                float c0 = ctab[t * 32 + i0], s0 = stab[t * 32 + i0];
                float c1 = ctab[t * 32 + i1], s1 = stab[t * 32 + i1];
                float e  = acc[i][j];
                float od = acc[i][j + 1];
                o[j]     = e * c0 - od * s0;
                o[j + 1] = od * c1 + e * s1;
            }
        } else {
#pragma unroll
            for (int j = 0; j < 8; j++) o[j] = acc[i][j];
        }
        float4* cp = (float4*)(C + (size_t)m * 1024 + nb);
        cp[0] = make_float4(o[0], o[1], o[2], o[3]);
        cp[1] = make_float4(o[4], o[5], o[6], o[7]);
    }
}

// ---------------- write path: slot_state[b,s,h,d] = (1/T) sum_t softmax_s(k.sk^T)*v ----
// grid (8, H, B), 256 threads. Each warp handles 64 t's; 64x64 partial in registers.
__global__ __launch_bounds__(256, 1)
void write_kernel(const float* __restrict__ gk, const float* __restrict__ gv,
                  const float* __restrict__ slot_keys, float* __restrict__ gslot) {
    __shared__ float sk[64 * 65];        // slot keys (padded); reused as reduce buffer
    __shared__ float kvs[8][2][64];      // per-warp k/v staging

    const int b = blockIdx.z, h = blockIdx.y, chunk = blockIdx.x;
    const int tid = threadIdx.x, w = tid >> 5, l = tid & 31;

    for (int idx = tid; idx < 4096; idx += 256) {
        int s = idx >> 6, d = idx & 63;
        sk[s * 65 + d] = slot_keys[((size_t)h * 64 + s) * 64 + d];
    }
    __syncthreads();

    float accL[64], accH[64];
#pragma unroll
    for (int d = 0; d < 64; d++) { accL[d] = 0.0f; accH[d] = 0.0f; }

    const float* skL = &sk[l * 65];
    const float* skH = &sk[(l + 32) * 65];
    const int t0 = chunk * 512 + w * 64;

    for (int tt = 0; tt < 64; tt++) {
        int t = t0 + tt;
        size_t row = ((size_t)b * Tc + t) * 1024 + h * 64;
        kvs[w][0][l] = gk[row + l];       kvs[w][0][l + 32] = gk[row + l + 32];
        kvs[w][1][l] = gv[row + l];       kvs[w][1][l + 32] = gv[row + l + 32];
        __syncwarp();

        float lo = 0.0f, hi = 0.0f;
#pragma unroll
        for (int d = 0; d < 64; d++) {
            float kd = kvs[w][0][d];
            lo += kd * skL[d];
            hi += kd * skH[d];
        }
        lo *= 0.125f; hi *= 0.125f;

        float mx = fmaxf(lo, hi);
#pragma unroll
        for (int off = 16; off; off >>= 1) mx = fmaxf(mx, __shfl_xor_sync(0xffffffffu, mx, off));
        float el = __expf(lo - mx), eh = __expf(hi - mx);
        float sm = el + eh;
#pragma unroll
        for (int off = 16; off; off >>= 1) sm += __shfl_xor_sync(0xffffffffu, sm, off);
        float inv = 1.0f / sm;
        float wl = el * inv, wh = eh * inv;

#pragma unroll
        for (int d = 0; d < 64; d++) {
            float vd = kvs[w][1][d];
            accL[d] += wl * vd;
            accH[d] += wh * vd;
        }
        __syncwarp();
    }

    // block reduce through smem (reuse sk region), then one global atomic pass
    __syncthreads();
    for (int idx = tid; idx < 64 * 65; idx += 256) sk[idx] = 0.0f;
    __syncthreads();
#pragma unroll
    for (int d = 0; d < 64; d++) {
        atomicAdd(&sk[l * 65 + d], accL[d]);
        atomicAdd(&sk[(l + 32) * 65 + d], accH[d]);
    }
    __syncthreads();
    float* base = gslot + ((size_t)(b * Hc + h)) * 4096;
    for (int idx = tid; idx < 4096; idx += 256) {
        int s = idx >> 6, d = idx & 63;
        atomicAdd(&base[idx], sk[s * 65 + d]);
    }
}

// ---------------- read path: ro[b,t,h,:] = softmax_s(q.ss^T * scale) @ ss ----------------
__global__ __launch_bounds__(256, 2)
void read_kernel(const float* __restrict__ gq, const float* __restrict__ gslot,
                 float* __restrict__ gro) {
    __shared__ float ss[64 * 65];
    __shared__ float qs[8][64];
    __shared__ float ws[8][64];

    const int b = blockIdx.z, h = blockIdx.y, chunk = blockIdx.x;
    const int tid = threadIdx.x, w = tid >> 5, l = tid & 31;

    const float* base = gslot + ((size_t)(b * Hc + h)) * 4096;
    const float invT = 1.0f / (float)Tc;
    for (int idx = tid; idx < 4096; idx += 256) {
        int s = idx >> 6, d = idx & 63;
        ss[s * 65 + d] = base[idx] * invT;   // fold /T here
    }
    __syncthreads();

    const float* ssL = &ss[l * 65];
    const float* ssH = &ss[(l + 32) * 65];
    const int t0 = chunk * 512 + w * 64;

    for (int tt = 0; tt < 64; tt++) {
        int t = t0 + tt;
        size_t row = ((size_t)b * Tc + t) * 1024 + h * 64;
        qs[w][l] = gq[row + l];  qs[w][l + 32] = gq[row + l + 32];
        __syncwarp();

        float lo = 0.0f, hi = 0.0f;
#pragma unroll
        for (int d = 0; d < 64; d++) {
            float qd = qs[w][d];
            lo += qd * ssL[d];
            hi += qd * ssH[d];
        }
        lo *= 0.125f; hi *= 0.125f;

        float mx = fmaxf(lo, hi);
#pragma unroll
        for (int off = 16; off; off >>= 1) mx = fmaxf(mx, __shfl_xor_sync(0xffffffffu, mx, off));
        float el = __expf(lo - mx), eh = __expf(hi - mx);
        float sm = el + eh;
#pragma unroll
        for (int off = 16; off; off >>= 1) sm += __shfl_xor_sync(0xffffffffu, sm, off);
        float inv = 1.0f / sm;
        ws[w][l] = el * inv;  ws[w][l + 32] = eh * inv;
        __syncwarp();

        float oL = 0.0f, oH = 0.0f;
#pragma unroll
        for (int s = 0; s < 64; s++) {
            float wv = ws[w][s];
            oL += wv * ss[s * 65 + l];
            oH += wv * ss[s * 65 + l + 32];
        }
        gro[row + l] = oL;
        gro[row + l + 32] = oH;
        __syncwarp();
    }
}

// ---------------- launch ----------------
extern "C" void kernel_launch(void* const* d_in, const int* in_sizes, int n_in,
                              void* d_out, int out_size) {
    (void)in_sizes; (void)n_in; (void)out_size;
    const float* x         = (const float*)d_in[0];
    const float* Wq        = (const float*)d_in[1];
    const float* Wk        = (const float*)d_in[2];
    const float* Wv        = (const float*)d_in[3];
    const float* Wout      = (const float*)d_in[4];
    const float* slot_keys = (const float*)d_in[5];
    float* out = (float*)d_out;

    float *pq, *pk, *pv, *pro, *pslot, *pcos, *psin;
    cudaGetSymbolAddress((void**)&pq,    g_q);
    cudaGetSymbolAddress((void**)&pk,    g_k);
    cudaGetSymbolAddress((void**)&pv,    g_v);
    cudaGetSymbolAddress((void**)&pro,   g_ro);
    cudaGetSymbolAddress((void**)&pslot, g_slot);
    cudaGetSymbolAddress((void**)&pcos,  g_cos);
    cudaGetSymbolAddress((void**)&psin,  g_sin);

    rope_table_kernel<<<Tc, 32>>>(pcos, psin);

    dim3 gg(Ec / 128, Mc / 128);   // (8, 128)
    sgemm128<1><<<gg, 256>>>(x, Wq, pq, pcos, psin);   // Q + RoPE
    sgemm128<1><<<gg, 256>>>(x, Wk, pk, pcos, psin);   // K + RoPE
    sgemm128<0><<<gg, 256>>>(x, Wv, pv, pcos, psin);   // V

    zero_kernel<<<(Bc * Hc * Sc * Dc + 255) / 256, 256>>>(pslot, Bc * Hc * Sc * Dc);

    write_kernel<<<dim3(8, Hc, Bc), 256>>>(pk, pv, slot_keys, pslot);
    read_kernel<<<dim3(8, Hc, Bc), 256>>>(pq, pslot, pro);

    sgemm128<0><<<gg, 256>>>(pro, Wout, out, pcos, psin);
}

// round 4
// speedup vs baseline: 1.9583x; 1.9583x over previous
#include <cuda_runtime.h>
#include <cuda_bf16.h>
#include <math.h>
#include <stdint.h>

// Problem constants
#define Bc 4
#define Tc 4096
#define Ec 1024
#define Hc 16
#define Sc 64
#define Dc 64
#define Mc (Bc * Tc)   // 16384

// ---------------- scratch (device globals: alloc-free rule) ----------------
__device__ float g_q[(size_t)Mc * Ec];
__device__ float g_k[(size_t)Mc * Ec];
__device__ float g_v[(size_t)Mc * Ec];
__device__ float g_ro[(size_t)Mc * Ec];
__device__ float g_slot[Bc * Hc * Sc * Dc];     // [b][h][s][d]
__device__ float g_cos[Tc * 32];
__device__ float g_sin[Tc * 32];

__device__ __nv_bfloat16 g_xhi[(size_t)Mc * Ec];
__device__ __nv_bfloat16 g_xlo[(size_t)Mc * Ec];
__device__ __nv_bfloat16 g_rohi[(size_t)Mc * Ec];
__device__ __nv_bfloat16 g_rolo[(size_t)Mc * Ec];
__device__ __nv_bfloat16 g_whi[4][(size_t)Ec * Ec];   // Wq, Wk, Wv, Wout
__device__ __nv_bfloat16 g_wlo[4][(size_t)Ec * Ec];

// ======================= helpers =======================
__device__ __forceinline__ uint32_t smem_u32(const void* p) {
    uint32_t a;
    asm("{ .reg .u64 t; cvta.to.shared.u64 t, %1; cvt.u32.u64 %0, t; }" : "=r"(a) : "l"(p));
    return a;
}
#define SWZ128(off) ((off) ^ (((off) >> 3) & 0x70))

__device__ __forceinline__ void cp_async16(uint32_t dst, const void* src) {
    asm volatile("cp.async.cg.shared.global [%0], [%1], 16;" :: "r"(dst), "l"(src) : "memory");
}
__device__ __forceinline__ void ldsm4(uint32_t* r, uint32_t addr) {
    asm volatile("ldmatrix.sync.aligned.m8n8.x4.shared.b16 {%0,%1,%2,%3}, [%4];"
        : "=r"(r[0]), "=r"(r[1]), "=r"(r[2]), "=r"(r[3]) : "r"(addr));
}
__device__ __forceinline__ void mma16816(float* d, const uint32_t* a, const uint32_t* b) {
    asm volatile("mma.sync.aligned.m16n8k16.row.col.f32.bf16.bf16.f32 "
        "{%0,%1,%2,%3}, {%4,%5,%6,%7}, {%8,%9}, {%0,%1,%2,%3};"
        : "+f"(d[0]), "+f"(d[1]), "+f"(d[2]), "+f"(d[3])
        : "r"(a[0]), "r"(a[1]), "r"(a[2]), "r"(a[3]), "r"(b[0]), "r"(b[1]));
}

// ---------------- rope tables ----------------
__global__ void rope_table_kernel(float* __restrict__ ct, float* __restrict__ st) {
    int t = blockIdx.x;
    int i = threadIdx.x;
    double p = pow(10000.0, -(double)i / 32.0);
    float ang = (float)t * (float)p;
    ct[t * 32 + i] = cosf(ang);
    st[t * 32 + i] = sinf(ang);
}

__global__ void zero_kernel(float* __restrict__ p, int n) {
    int i = blockIdx.x * 256 + threadIdx.x;
    if (i < n) p[i] = 0.0f;
}

// ---------------- fp32 -> bf16 hi/lo split ----------------
__global__ void split_kernel(const float* __restrict__ in,
                             __nv_bfloat16* __restrict__ hi,
                             __nv_bfloat16* __restrict__ lo, int n4) {
    int i = blockIdx.x * 256 + threadIdx.x;
    if (i >= n4) return;
    float4 v = ((const float4*)in)[i];
    float vv[4] = {v.x, v.y, v.z, v.w};
    __align__(8) __nv_bfloat16 h[4];
    __align__(8) __nv_bfloat16 l[4];
#pragma unroll
    for (int j = 0; j < 4; j++) {
        h[j] = __float2bfloat16_rn(vv[j]);
        l[j] = __float2bfloat16_rn(vv[j] - __bfloat162float(h[j]));
    }
    *(uint2*)(hi + 4 * (size_t)i) = *(const uint2*)h;
    *(uint2*)(lo + 4 * (size_t)i) = *(const uint2*)l;
}

// ======================= split-bf16 NT GEMM on HMMA (mma.sync) =======================
// C[m][n] = sum_k A[m][k]*B[n][k], M=16384, N=K=1024.
// Block tile 128x128, K-chunk 64. 8 warps as 4(m) x 2(n); warp tile 32x64.
// Smem: 3 stages x (Ahi,Alo,Bhi,Blo) x (128 rows x 128B, SW128 swizzled).
#define NSTAGES 3
#define TILE_B 16384
#define STAGE_B (4 * TILE_B)
#define GEMM_SMEM (NSTAGES * STAGE_B)

template <int ROPE>
__global__ void __launch_bounds__(256, 1)
tc_gemm(const __nv_bfloat16* __restrict__ Ahi, const __nv_bfloat16* __restrict__ Alo,
        const __nv_bfloat16* __restrict__ Bhi, const __nv_bfloat16* __restrict__ Blo,
        float* __restrict__ C,
        const float* __restrict__ ctab, const float* __restrict__ stab) {
    extern __shared__ char smem[];
    const uint32_t sb = smem_u32(smem);
    const int tid = threadIdx.x;
    const int wid = tid >> 5, lane = tid & 31;
    const int wm = wid >> 1;            // 0..3 (m)
    const int wn = wid & 1;             // 0..1 (n)
    const int bn = blockIdx.x, bm = blockIdx.y;

    const __nv_bfloat16* bp[4];
    bp[0] = Ahi + (size_t)bm * 128 * 1024;
    bp[1] = Alo + (size_t)bm * 128 * 1024;
    bp[2] = Bhi + (size_t)bn * 128 * 1024;
    bp[3] = Blo + (size_t)bn * 128 * 1024;

    auto load_chunk = [&](int c, int st) {
        const uint32_t stbase = sb + st * STAGE_B;
        const int k0 = c * 64;
#pragma unroll
        for (int i = 0; i < 16; i++) {
            const int sub = i >> 2;
            const int rc = (i & 3) * 256 + tid;   // 0..1023
            const int row = rc >> 3;
            const int seg = rc & 7;
            uint32_t off = (uint32_t)row * 128 + seg * 16;
            uint32_t dst = stbase + sub * TILE_B + SWZ128(off);
            cp_async16(dst, bp[sub] + (size_t)row * 1024 + (k0 + seg * 8));
        }
    };

    float acc[2][8][4];
#pragma unroll
    for (int mt = 0; mt < 2; mt++)
#pragma unroll
        for (int nt = 0; nt < 8; nt++)
#pragma unroll
            for (int r = 0; r < 4; r++) acc[mt][nt][r] = 0.0f;

    load_chunk(0, 0); asm volatile("cp.async.commit_group;" ::: "memory");
    load_chunk(1, 1); asm volatile("cp.async.commit_group;" ::: "memory");

    // per-lane ldmatrix address components
    const int lrow = lane & 15;         // row within 16-row block
    const int lhalf = lane >> 4;        // k half (0/1): +16B

    for (int c = 0; c < 16; c++) {
        const int st = c - (c >= 15 ? 15 : (c >= 12 ? 12 : (c >= 9 ? 9 : (c >= 6 ? 6 : (c >= 3 ? 3 : 0)))));
        const uint32_t stbase = sb + (uint32_t)(c % 3) * STAGE_B;
        asm volatile("cp.async.wait_group 1;" ::: "memory");
        __syncthreads();
        (void)st;

        const uint32_t aHi = stbase;
        const uint32_t aLo = stbase + TILE_B;
        const uint32_t bHi = stbase + 2 * TILE_B;
        const uint32_t bLo = stbase + 3 * TILE_B;

#pragma unroll
        for (int ks = 0; ks < 4; ks++) {
            const uint32_t kb = ks * 32 + lhalf * 16;
            uint32_t ah[2][4], al[2][4], bh[8][2], bl[8][2];
#pragma unroll
            for (int mt = 0; mt < 2; mt++) {
                uint32_t ro = (uint32_t)(wm * 32 + mt * 16 + lrow) * 128 + kb;
                ldsm4(ah[mt], aHi + SWZ128(ro));
                ldsm4(al[mt], aLo + SWZ128(ro));
            }
#pragma unroll
            for (int nq = 0; nq < 4; nq++) {
                uint32_t ro = (uint32_t)(wn * 64 + nq * 16 + lrow) * 128 + kb;
                uint32_t r4[4];
                ldsm4(r4, bHi + SWZ128(ro));
                bh[nq * 2][0] = r4[0]; bh[nq * 2][1] = r4[2];
                bh[nq * 2 + 1][0] = r4[1]; bh[nq * 2 + 1][1] = r4[3];
                ldsm4(r4, bLo + SWZ128(ro));
                bl[nq * 2][0] = r4[0]; bl[nq * 2][1] = r4[2];
                bl[nq * 2 + 1][0] = r4[1]; bl[nq * 2 + 1][1] = r4[3];
            }
#pragma unroll
            for (int mt = 0; mt < 2; mt++)
#pragma unroll
                for (int nt = 0; nt < 8; nt++) {
                    mma16816(acc[mt][nt], ah[mt], bh[nt]);
                    mma16816(acc[mt][nt], ah[mt], bl[nt]);
                    mma16816(acc[mt][nt], al[mt], bh[nt]);
                }
        }
        __syncthreads();
        if (c + 2 < 16) load_chunk(c + 2, (c + 2) % 3);
        asm volatile("cp.async.commit_group;" ::: "memory");
    }
    __syncthreads();

    // ---- epilogue: (RoPE) -> smem stage -> coalesced store ----
    float* stg = (float*)smem;          // 128 x 132 floats = 67.6KB < 192KB
    const int qr = lane >> 2;           // 0..7
    const int qc = (lane & 3) * 2;      // 0,2,4,6
#pragma unroll
    for (int mt = 0; mt < 2; mt++) {
#pragma unroll
        for (int nt = 0; nt < 8; nt++) {
            const int c0 = wn * 64 + nt * 8 + qc;
#pragma unroll
            for (int half = 0; half < 2; half++) {
                const int r = wm * 32 + mt * 16 + half * 8 + qr;
                float e = acc[mt][nt][half * 2];
                float od = acc[mt][nt][half * 2 + 1];
                if (ROPE) {
                    const int t = (bm * 128 + r) & (Tc - 1);
                    const int i0 = (nt * 8 + qc) & 31;
                    const float cc0 = ctab[t * 32 + i0], ss0 = stab[t * 32 + i0];
                    const float cc1 = ctab[t * 32 + i0 + 1], ss1 = stab[t * 32 + i0 + 1];
                    const float ne = e * cc0 - od * ss0;
                    const float no = od * cc1 + e * ss1;
                    e = ne; od = no;
                }
                stg[r * 132 + c0] = e;
                stg[r * 132 + c0 + 1] = od;
            }
        }
    }
    __syncthreads();
#pragma unroll
    for (int i = 0; i < 16; i++) {
        const int idx = i * 256 + tid;
        const int r = idx >> 5, c4 = (idx & 31) * 4;
        *(float4*)&C[(size_t)(bm * 128 + r) * 1024 + bn * 128 + c4] =
            *(const float4*)&stg[r * 132 + c4];
    }
}

// ---------------- write path (unchanged, passing) ----------------
__global__ __launch_bounds__(256, 1)
void write_kernel(const float* __restrict__ gk, const float* __restrict__ gv,
                  const float* __restrict__ slot_keys, float* __restrict__ gslot) {
    __shared__ float sk[64 * 65];
    __shared__ float kvs[8][2][64];

    const int b = blockIdx.z, h = blockIdx.y, chunk = blockIdx.x;
    const int tid = threadIdx.x, w = tid >> 5, l = tid & 31;

    for (int idx = tid; idx < 4096; idx += 256) {
        int s = idx >> 6, d = idx & 63;
        sk[s * 65 + d] = slot_keys[((size_t)h * 64 + s) * 64 + d];
    }
    __syncthreads();

    float accL[64], accH[64];
#pragma unroll
    for (int d = 0; d < 64; d++) { accL[d] = 0.0f; accH[d] = 0.0f; }

    const float* skL = &sk[l * 65];
    const float* skH = &sk[(l + 32) * 65];
    const int t0 = chunk * 512 + w * 64;

    for (int tt = 0; tt < 64; tt++) {
        int t = t0 + tt;
        size_t row = ((size_t)b * Tc + t) * 1024 + h * 64;
        kvs[w][0][l] = gk[row + l];       kvs[w][0][l + 32] = gk[row + l + 32];
        kvs[w][1][l] = gv[row + l];       kvs[w][1][l + 32] = gv[row + l + 32];
        __syncwarp();

        float lo = 0.0f, hi = 0.0f;
#pragma unroll
        for (int d = 0; d < 64; d++) {
            float kd = kvs[w][0][d];
            lo += kd * skL[d];
            hi += kd * skH[d];
        }
        lo *= 0.125f; hi *= 0.125f;

        float mx = fmaxf(lo, hi);
#pragma unroll
        for (int off = 16; off; off >>= 1) mx = fmaxf(mx, __shfl_xor_sync(0xffffffffu, mx, off));
        float el = __expf(lo - mx), eh = __expf(hi - mx);
        float sm = el + eh;
#pragma unroll
        for (int off = 16; off; off >>= 1) sm += __shfl_xor_sync(0xffffffffu, sm, off);
        float inv = 1.0f / sm;
        float wl = el * inv, wh = eh * inv;

#pragma unroll
        for (int d = 0; d < 64; d++) {
            float vd = kvs[w][1][d];
            accL[d] += wl * vd;
            accH[d] += wh * vd;
        }
        __syncwarp();
    }

    __syncthreads();
    for (int idx = tid; idx < 64 * 65; idx += 256) sk[idx] = 0.0f;
    __syncthreads();
#pragma unroll
    for (int d = 0; d < 64; d++) {
        atomicAdd(&sk[l * 65 + d], accL[d]);
        atomicAdd(&sk[(l + 32) * 65 + d], accH[d]);
    }
    __syncthreads();
    float* base = gslot + ((size_t)(b * Hc + h)) * 4096;
    for (int idx = tid; idx < 4096; idx += 256) {
        int s = idx >> 6, d = idx & 63;
        atomicAdd(&base[idx], sk[s * 65 + d]);
    }
}

// ---------------- read path (unchanged, passing) ----------------
__global__ __launch_bounds__(256, 2)
void read_kernel(const float* __restrict__ gq, const float* __restrict__ gslot,
                 float* __restrict__ gro) {
    __shared__ float ss[64 * 65];
    __shared__ float qs[8][64];
    __shared__ float ws[8][64];

    const int b = blockIdx.z, h = blockIdx.y, chunk = blockIdx.x;
    const int tid = threadIdx.x, w = tid >> 5, l = tid & 31;

    const float* base = gslot + ((size_t)(b * Hc + h)) * 4096;
    const float invT = 1.0f / (float)Tc;
    for (int idx = tid; idx < 4096; idx += 256) {
        int s = idx >> 6, d = idx & 63;
        ss[s * 65 + d] = base[idx] * invT;
    }
    __syncthreads();

    const float* ssL = &ss[l * 65];
    const float* ssH = &ss[(l + 32) * 65];
    const int t0 = chunk * 512 + w * 64;

    for (int tt = 0; tt < 64; tt++) {
        int t = t0 + tt;
        size_t row = ((size_t)b * Tc + t) * 1024 + h * 64;
        qs[w][l] = gq[row + l];  qs[w][l + 32] = gq[row + l + 32];
        __syncwarp();

        float lo = 0.0f, hi = 0.0f;
#pragma unroll
        for (int d = 0; d < 64; d++) {
            float qd = qs[w][d];
            lo += qd * ssL[d];
            hi += qd * ssH[d];
        }
        lo *= 0.125f; hi *= 0.125f;

        float mx = fmaxf(lo, hi);
#pragma unroll
        for (int off = 16; off; off >>= 1) mx = fmaxf(mx, __shfl_xor_sync(0xffffffffu, mx, off));
        float el = __expf(lo - mx), eh = __expf(hi - mx);
        float sm = el + eh;
#pragma unroll
        for (int off = 16; off; off >>= 1) sm += __shfl_xor_sync(0xffffffffu, sm, off);
        float inv = 1.0f / sm;
        ws[w][l] = el * inv;  ws[w][l + 32] = eh * inv;
        __syncwarp();

        float oL = 0.0f, oH = 0.0f;
#pragma unroll
        for (int s = 0; s < 64; s++) {
            float wv = ws[w][s];
            oL += wv * ss[s * 65 + l];
            oH += wv * ss[s * 65 + l + 32];
        }
        gro[row + l] = oL;
        gro[row + l + 32] = oH;
        __syncwarp();
    }
}

// ---------------- launch ----------------
extern "C" void kernel_launch(void* const* d_in, const int* in_sizes, int n_in,
                              void* d_out, int out_size) {
    (void)in_sizes; (void)n_in; (void)out_size;
    const float* x         = (const float*)d_in[0];
    const float* Wq        = (const float*)d_in[1];
    const float* Wk        = (const float*)d_in[2];
    const float* Wv        = (const float*)d_in[3];
    const float* Wout      = (const float*)d_in[4];
    const float* slot_keys = (const float*)d_in[5];
    float* out = (float*)d_out;

    float *pq, *pk, *pv, *pro, *pslot, *pcos, *psin;
    cudaGetSymbolAddress((void**)&pq,    g_q);
    cudaGetSymbolAddress((void**)&pk,    g_k);
    cudaGetSymbolAddress((void**)&pv,    g_v);
    cudaGetSymbolAddress((void**)&pro,   g_ro);
    cudaGetSymbolAddress((void**)&pslot, g_slot);
    cudaGetSymbolAddress((void**)&pcos,  g_cos);
    cudaGetSymbolAddress((void**)&psin,  g_sin);

    __nv_bfloat16 *xhi, *xlo, *rohi, *rolo, *whi, *wlo;
    cudaGetSymbolAddress((void**)&xhi,  g_xhi);
    cudaGetSymbolAddress((void**)&xlo,  g_xlo);
    cudaGetSymbolAddress((void**)&rohi, g_rohi);
    cudaGetSymbolAddress((void**)&rolo, g_rolo);
    cudaGetSymbolAddress((void**)&whi,  g_whi);
    cudaGetSymbolAddress((void**)&wlo,  g_wlo);
    const size_t WSZ = (size_t)Ec * Ec;

    cudaFuncSetAttribute(tc_gemm<0>, cudaFuncAttributeMaxDynamicSharedMemorySize, GEMM_SMEM);
    cudaFuncSetAttribute(tc_gemm<1>, cudaFuncAttributeMaxDynamicSharedMemorySize, GEMM_SMEM);

    rope_table_kernel<<<Tc, 32>>>(pcos, psin);

    // splits
    split_kernel<<<(Mc * Ec / 4 + 255) / 256, 256>>>(x, xhi, xlo, Mc * Ec / 4);
    split_kernel<<<(int)(WSZ / 4 + 255) / 256, 256>>>(Wq,   whi + 0 * WSZ, wlo + 0 * WSZ, (int)(WSZ / 4));
    split_kernel<<<(int)(WSZ / 4 + 255) / 256, 256>>>(Wk,   whi + 1 * WSZ, wlo + 1 * WSZ, (int)(WSZ / 4));
    split_kernel<<<(int)(WSZ / 4 + 255) / 256, 256>>>(Wv,   whi + 2 * WSZ, wlo + 2 * WSZ, (int)(WSZ / 4));
    split_kernel<<<(int)(WSZ / 4 + 255) / 256, 256>>>(Wout, whi + 3 * WSZ, wlo + 3 * WSZ, (int)(WSZ / 4));

    dim3 gg(Ec / 128, Mc / 128);   // (8, 128)
    tc_gemm<1><<<gg, 256, GEMM_SMEM>>>(xhi, xlo, whi + 0 * WSZ, wlo + 0 * WSZ, pq, pcos, psin);
    tc_gemm<1><<<gg, 256, GEMM_SMEM>>>(xhi, xlo, whi + 1 * WSZ, wlo + 1 * WSZ, pk, pcos, psin);
    tc_gemm<0><<<gg, 256, GEMM_SMEM>>>(xhi, xlo, whi + 2 * WSZ, wlo + 2 * WSZ, pv, pcos, psin);

    zero_kernel<<<(Bc * Hc * Sc * Dc + 255) / 256, 256>>>(pslot, Bc * Hc * Sc * Dc);

    write_kernel<<<dim3(8, Hc, Bc), 256>>>(pk, pv, slot_keys, pslot);
    read_kernel<<<dim3(8, Hc, Bc), 256>>>(pq, pslot, pro);

    split_kernel<<<(Mc * Ec / 4 + 255) / 256, 256>>>(pro, rohi, rolo, Mc * Ec / 4);
    tc_gemm<0><<<gg, 256, GEMM_SMEM>>>(rohi, rolo, whi + 3 * WSZ, wlo + 3 * WSZ, out, pcos, psin);
}

// round 5
// speedup vs baseline: 2.0145x; 1.0287x over previous
#include <cuda_runtime.h>
#include <cuda_bf16.h>
#include <math.h>
#include <stdint.h>

// Problem constants
#define Bc 4
#define Tc 4096
#define Ec 1024
#define Hc 16
#define Sc 64
#define Dc 64
#define Mc (Bc * Tc)   // 16384

// ---------------- scratch (device globals: alloc-free rule) ----------------
__device__ float g_q[(size_t)Mc * Ec];
__device__ float g_k[(size_t)Mc * Ec];
__device__ float g_v[(size_t)Mc * Ec];
__device__ float g_ro[(size_t)Mc * Ec];
__device__ float g_slot[Bc * Hc * Sc * Dc];     // [b][h][s][d]
__device__ float g_cos[Tc * 32];
__device__ float g_sin[Tc * 32];

__device__ __nv_bfloat16 g_xhi[(size_t)Mc * Ec];
__device__ __nv_bfloat16 g_xlo[(size_t)Mc * Ec];
__device__ __nv_bfloat16 g_rohi[(size_t)Mc * Ec];
__device__ __nv_bfloat16 g_rolo[(size_t)Mc * Ec];
__device__ __nv_bfloat16 g_whi[4][(size_t)Ec * Ec];   // Wq, Wk, Wv, Wout
__device__ __nv_bfloat16 g_wlo[4][(size_t)Ec * Ec];

// ======================= helpers =======================
__device__ __forceinline__ uint32_t smem_u32(const void* p) {
    uint32_t a;
    asm("{ .reg .u64 t; cvta.to.shared.u64 t, %1; cvt.u32.u64 %0, t; }" : "=r"(a) : "l"(p));
    return a;
}
#define SWZ64(off) ((off) ^ (((off) >> 3) & 0x30))

__device__ __forceinline__ void cp_async16(uint32_t dst, const void* src) {
    asm volatile("cp.async.cg.shared.global [%0], [%1], 16;" :: "r"(dst), "l"(src) : "memory");
}
__device__ __forceinline__ void ldsm4(uint32_t* r, uint32_t addr) {
    asm volatile("ldmatrix.sync.aligned.m8n8.x4.shared.b16 {%0,%1,%2,%3}, [%4];"
        : "=r"(r[0]), "=r"(r[1]), "=r"(r[2]), "=r"(r[3]) : "r"(addr));
}
__device__ __forceinline__ void mma16816(float* d, const uint32_t* a, uint32_t b0, uint32_t b1) {
    asm volatile("mma.sync.aligned.m16n8k16.row.col.f32.bf16.bf16.f32 "
        "{%0,%1,%2,%3}, {%4,%5,%6,%7}, {%8,%9}, {%0,%1,%2,%3};"
        : "+f"(d[0]), "+f"(d[1]), "+f"(d[2]), "+f"(d[3])
        : "r"(a[0]), "r"(a[1]), "r"(a[2]), "r"(a[3]), "r"(b0), "r"(b1));
}

// ---------------- rope tables ----------------
__global__ void rope_table_kernel(float* __restrict__ ct, float* __restrict__ st) {
    int t = blockIdx.x;
    int i = threadIdx.x;
    double p = pow(10000.0, -(double)i / 32.0);
    float ang = (float)t * (float)p;
    ct[t * 32 + i] = cosf(ang);
    st[t * 32 + i] = sinf(ang);
}

__global__ void zero_kernel(float* __restrict__ p, int n) {
    int i = blockIdx.x * 256 + threadIdx.x;
    if (i < n) p[i] = 0.0f;
}

// ---------------- fp32 -> bf16 hi/lo split ----------------
__global__ void split_kernel(const float* __restrict__ in,
                             __nv_bfloat16* __restrict__ hi,
                             __nv_bfloat16* __restrict__ lo, int n4) {
    int i = blockIdx.x * 256 + threadIdx.x;
    if (i >= n4) return;
    float4 v = ((const float4*)in)[i];
    float vv[4] = {v.x, v.y, v.z, v.w};
    __align__(8) __nv_bfloat16 h[4];
    __align__(8) __nv_bfloat16 l[4];
#pragma unroll
    for (int j = 0; j < 4; j++) {
        h[j] = __float2bfloat16_rn(vv[j]);
        l[j] = __float2bfloat16_rn(vv[j] - __bfloat162float(h[j]));
    }
    *(uint2*)(hi + 4 * (size_t)i) = *(const uint2*)h;
    *(uint2*)(lo + 4 * (size_t)i) = *(const uint2*)l;
}

// ======================= split-bf16 NT GEMM on HMMA (mma.sync) =======================
// C[m][n] = sum_k A[m][k]*B[n][k], M=16384, N=K=1024.
// Block tile 128x128, K-chunk 32 (64B rows, SW64). 8 warps as 4(m) x 2(n); warp 32x64.
// 3 stages x 4 tiles x 8KB = 96KB smem -> 2 CTAs/SM.
#define NSTAGES 3
#define TILE_B 8192
#define STAGE_B (4 * TILE_B)
#define GEMM_SMEM (NSTAGES * STAGE_B)
#define NCHUNK 32

template <int ROPE>
__global__ void __launch_bounds__(256, 2)
tc_gemm(const __nv_bfloat16* __restrict__ Ahi, const __nv_bfloat16* __restrict__ Alo,
        const __nv_bfloat16* __restrict__ Bhi, const __nv_bfloat16* __restrict__ Blo,
        float* __restrict__ C,
        const float* __restrict__ ctab, const float* __restrict__ stab) {
    extern __shared__ char smem[];
    const uint32_t sb = smem_u32(smem);
    const int tid = threadIdx.x;
    const int wid = tid >> 5, lane = tid & 31;
    const int wm = wid >> 1;            // 0..3 (m)
    const int wn = wid & 1;             // 0..1 (n)
    const int bn = blockIdx.x, bm = blockIdx.y;

    const __nv_bfloat16* bp[4];
    bp[0] = Ahi + (size_t)bm * 128 * 1024;
    bp[1] = Alo + (size_t)bm * 128 * 1024;
    bp[2] = Bhi + (size_t)bn * 128 * 1024;
    bp[3] = Blo + (size_t)bn * 128 * 1024;

    // 512 cp.async16 per chunk, 2 per thread per sub-tile
    auto load_chunk = [&](int c, int st) {
        const uint32_t stbase = sb + st * STAGE_B;
        const int k0 = c * 32;
#pragma unroll
        for (int i = 0; i < 8; i++) {
            const int sub = i >> 1;
            const int rc = (i & 1) * 256 + tid;   // 0..511
            const int row = rc >> 2;
            const int seg = rc & 3;
            uint32_t off = (uint32_t)row * 64 + seg * 16;
            uint32_t dst = stbase + sub * TILE_B + SWZ64(off);
            cp_async16(dst, bp[sub] + (size_t)row * 1024 + (k0 + seg * 8));
        }
    };

    float acc[2][8][4];
#pragma unroll
    for (int mt = 0; mt < 2; mt++)
#pragma unroll
        for (int nt = 0; nt < 8; nt++)
#pragma unroll
            for (int r = 0; r < 4; r++) acc[mt][nt][r] = 0.0f;

    load_chunk(0, 0); asm volatile("cp.async.commit_group;" ::: "memory");
    load_chunk(1, 1); asm volatile("cp.async.commit_group;" ::: "memory");

    // precomputed swizzled ldmatrix row bases (XOR kb later; valid since kb<64
    // and row*64 has zero low 6 bits -> add == xor in those bits)
    const int lrow = lane & 15;
    const uint32_t lkb = (uint32_t)(lane >> 4) * 16;   // k-half offset
    uint32_t aswz[2], bswz[4];
#pragma unroll
    for (int mt = 0; mt < 2; mt++)
        aswz[mt] = SWZ64((uint32_t)(wm * 32 + mt * 16 + lrow) * 64);
#pragma unroll
    for (int nq = 0; nq < 4; nq++)
        bswz[nq] = SWZ64((uint32_t)(wn * 64 + nq * 16 + lrow) * 64);

    for (int c = 0; c < NCHUNK; c++) {
        const uint32_t stbase = sb + (uint32_t)(c % 3) * STAGE_B;
        asm volatile("cp.async.wait_group 1;" ::: "memory");
        __syncthreads();

        const uint32_t aHi = stbase;
        const uint32_t aLo = stbase + TILE_B;
        const uint32_t bHi = stbase + 2 * TILE_B;
        const uint32_t bLo = stbase + 3 * TILE_B;

#pragma unroll
        for (int ks = 0; ks < 2; ks++) {
            const uint32_t kb = (uint32_t)ks * 32 ^ lkb;
            uint32_t ah[2][4], al[2][4];
#pragma unroll
            for (int mt = 0; mt < 2; mt++) {
                ldsm4(ah[mt], aHi + (aswz[mt] ^ kb));
                ldsm4(al[mt], aLo + (aswz[mt] ^ kb));
            }
#pragma unroll
            for (int nq = 0; nq < 4; nq++) {
                uint32_t rh[4], rl[4];
                ldsm4(rh, bHi + (bswz[nq] ^ kb));
                ldsm4(rl, bLo + (bswz[nq] ^ kb));
#pragma unroll
                for (int mt = 0; mt < 2; mt++) {
                    mma16816(acc[mt][nq * 2],     ah[mt], rh[0], rh[2]);
                    mma16816(acc[mt][nq * 2],     ah[mt], rl[0], rl[2]);
                    mma16816(acc[mt][nq * 2],     al[mt], rh[0], rh[2]);
                    mma16816(acc[mt][nq * 2 + 1], ah[mt], rh[1], rh[3]);
                    mma16816(acc[mt][nq * 2 + 1], ah[mt], rl[1], rl[3]);
                    mma16816(acc[mt][nq * 2 + 1], al[mt], rh[1], rh[3]);
                }
            }
        }
        if (c + 2 < NCHUNK) load_chunk(c + 2, (c + 2) % 3);
        asm volatile("cp.async.commit_group;" ::: "memory");
    }
    __syncthreads();

    // ---- epilogue: (RoPE) -> smem stage -> coalesced store ----
    float* stg = (float*)smem;          // 128 x 132 floats = 67.6KB < 96KB
    const int qr = lane >> 2;           // 0..7
    const int qc = (lane & 3) * 2;      // 0,2,4,6
#pragma unroll
    for (int mt = 0; mt < 2; mt++) {
#pragma unroll
        for (int nt = 0; nt < 8; nt++) {
            const int c0 = wn * 64 + nt * 8 + qc;
#pragma unroll
            for (int half = 0; half < 2; half++) {
                const int r = wm * 32 + mt * 16 + half * 8 + qr;
                float e = acc[mt][nt][half * 2];
                float od = acc[mt][nt][half * 2 + 1];
                if (ROPE) {
                    const int t = (bm * 128 + r) & (Tc - 1);
                    const int i0 = (nt * 8 + qc) & 31;
                    const float cc0 = ctab[t * 32 + i0], ss0 = stab[t * 32 + i0];
                    const float cc1 = ctab[t * 32 + i0 + 1], ss1 = stab[t * 32 + i0 + 1];
                    const float ne = e * cc0 - od * ss0;
                    const float no = od * cc1 + e * ss1;
                    e = ne; od = no;
                }
                stg[r * 132 + c0] = e;
                stg[r * 132 + c0 + 1] = od;
            }
        }
    }
    __syncthreads();
#pragma unroll
    for (int i = 0; i < 16; i++) {
        const int idx = i * 256 + tid;
        const int r = idx >> 5, c4 = (idx & 31) * 4;
        *(float4*)&C[(size_t)(bm * 128 + r) * 1024 + bn * 128 + c4] =
            *(const float4*)&stg[r * 132 + c4];
    }
}

// ---------------- write path (unchanged, passing) ----------------
__global__ __launch_bounds__(256, 1)
void write_kernel(const float* __restrict__ gk, const float* __restrict__ gv,
                  const float* __restrict__ slot_keys, float* __restrict__ gslot) {
    __shared__ float sk[64 * 65];
    __shared__ float kvs[8][2][64];

    const int b = blockIdx.z, h = blockIdx.y, chunk = blockIdx.x;
    const int tid = threadIdx.x, w = tid >> 5, l = tid & 31;

    for (int idx = tid; idx < 4096; idx += 256) {
        int s = idx >> 6, d = idx & 63;
        sk[s * 65 + d] = slot_keys[((size_t)h * 64 + s) * 64 + d];
    }
    __syncthreads();

    float accL[64], accH[64];
#pragma unroll
    for (int d = 0; d < 64; d++) { accL[d] = 0.0f; accH[d] = 0.0f; }

    const float* skL = &sk[l * 65];
    const float* skH = &sk[(l + 32) * 65];
    const int t0 = chunk * 512 + w * 64;

    for (int tt = 0; tt < 64; tt++) {
        int t = t0 + tt;
        size_t row = ((size_t)b * Tc + t) * 1024 + h * 64;
        kvs[w][0][l] = gk[row + l];       kvs[w][0][l + 32] = gk[row + l + 32];
        kvs[w][1][l] = gv[row + l];       kvs[w][1][l + 32] = gv[row + l + 32];
        __syncwarp();

        float lo = 0.0f, hi = 0.0f;
#pragma unroll
        for (int d = 0; d < 64; d++) {
            float kd = kvs[w][0][d];
            lo += kd * skL[d];
            hi += kd * skH[d];
        }
        lo *= 0.125f; hi *= 0.125f;

        float mx = fmaxf(lo, hi);
#pragma unroll
        for (int off = 16; off; off >>= 1) mx = fmaxf(mx, __shfl_xor_sync(0xffffffffu, mx, off));
        float el = __expf(lo - mx), eh = __expf(hi - mx);
        float sm = el + eh;
#pragma unroll
        for (int off = 16; off; off >>= 1) sm += __shfl_xor_sync(0xffffffffu, sm, off);
        float inv = 1.0f / sm;
        float wl = el * inv, wh = eh * inv;

#pragma unroll
        for (int d = 0; d < 64; d++) {
            float vd = kvs[w][1][d];
            accL[d] += wl * vd;
            accH[d] += wh * vd;
        }
        __syncwarp();
    }

    __syncthreads();
    for (int idx = tid; idx < 64 * 65; idx += 256) sk[idx] = 0.0f;
    __syncthreads();
#pragma unroll
    for (int d = 0; d < 64; d++) {
        atomicAdd(&sk[l * 65 + d], accL[d]);
        atomicAdd(&sk[(l + 32) * 65 + d], accH[d]);
    }
    __syncthreads();
    float* base = gslot + ((size_t)(b * Hc + h)) * 4096;
    for (int idx = tid; idx < 4096; idx += 256) {
        int s = idx >> 6, d = idx & 63;
        atomicAdd(&base[idx], sk[s * 65 + d]);
    }
}

// ---------------- read path (unchanged, passing) ----------------
__global__ __launch_bounds__(256, 2)
void read_kernel(const float* __restrict__ gq, const float* __restrict__ gslot,
                 float* __restrict__ gro) {
    __shared__ float ss[64 * 65];
    __shared__ float qs[8][64];
    __shared__ float ws[8][64];

    const int b = blockIdx.z, h = blockIdx.y, chunk = blockIdx.x;
    const int tid = threadIdx.x, w = tid >> 5, l = tid & 31;

    const float* base = gslot + ((size_t)(b * Hc + h)) * 4096;
    const float invT = 1.0f / (float)Tc;
    for (int idx = tid; idx < 4096; idx += 256) {
        int s = idx >> 6, d = idx & 63;
        ss[s * 65 + d] = base[idx] * invT;
    }
    __syncthreads();

    const float* ssL = &ss[l * 65];
    const float* ssH = &ss[(l + 32) * 65];
    const int t0 = chunk * 512 + w * 64;

    for (int tt = 0; tt < 64; tt++) {
        int t = t0 + tt;
        size_t row = ((size_t)b * Tc + t) * 1024 + h * 64;
        qs[w][l] = gq[row + l];  qs[w][l + 32] = gq[row + l + 32];
        __syncwarp();

        float lo = 0.0f, hi = 0.0f;
#pragma unroll
        for (int d = 0; d < 64; d++) {
            float qd = qs[w][d];
            lo += qd * ssL[d];
            hi += qd * ssH[d];
        }
        lo *= 0.125f; hi *= 0.125f;

        float mx = fmaxf(lo, hi);
#pragma unroll
        for (int off = 16; off; off >>= 1) mx = fmaxf(mx, __shfl_xor_sync(0xffffffffu, mx, off));
        float el = __expf(lo - mx), eh = __expf(hi - mx);
        float sm = el + eh;
#pragma unroll
        for (int off = 16; off; off >>= 1) sm += __shfl_xor_sync(0xffffffffu, sm, off);
        float inv = 1.0f / sm;
        ws[w][l] = el * inv;  ws[w][l + 32] = eh * inv;
        __syncwarp();

        float oL = 0.0f, oH = 0.0f;
#pragma unroll
        for (int s = 0; s < 64; s++) {
            float wv = ws[w][s];
            oL += wv * ss[s * 65 + l];
            oH += wv * ss[s * 65 + l + 32];
        }
        gro[row + l] = oL;
        gro[row + l + 32] = oH;
        __syncwarp();
    }
}

// ---------------- launch ----------------
extern "C" void kernel_launch(void* const* d_in, const int* in_sizes, int n_in,
                              void* d_out, int out_size) {
    (void)in_sizes; (void)n_in; (void)out_size;
    const float* x         = (const float*)d_in[0];
    const float* Wq        = (const float*)d_in[1];
    const float* Wk        = (const float*)d_in[2];
    const float* Wv        = (const float*)d_in[3];
    const float* Wout      = (const float*)d_in[4];
    const float* slot_keys = (const float*)d_in[5];
    float* out = (float*)d_out;

    float *pq, *pk, *pv, *pro, *pslot, *pcos, *psin;
    cudaGetSymbolAddress((void**)&pq,    g_q);
    cudaGetSymbolAddress((void**)&pk,    g_k);
    cudaGetSymbolAddress((void**)&pv,    g_v);
    cudaGetSymbolAddress((void**)&pro,   g_ro);
    cudaGetSymbolAddress((void**)&pslot, g_slot);
    cudaGetSymbolAddress((void**)&pcos,  g_cos);
    cudaGetSymbolAddress((void**)&psin,  g_sin);

    __nv_bfloat16 *xhi, *xlo, *rohi, *rolo, *whi, *wlo;
    cudaGetSymbolAddress((void**)&xhi,  g_xhi);
    cudaGetSymbolAddress((void**)&xlo,  g_xlo);
    cudaGetSymbolAddress((void**)&rohi, g_rohi);
    cudaGetSymbolAddress((void**)&rolo, g_rolo);
    cudaGetSymbolAddress((void**)&whi,  g_whi);
    cudaGetSymbolAddress((void**)&wlo,  g_wlo);
    const size_t WSZ = (size_t)Ec * Ec;

    cudaFuncSetAttribute(tc_gemm<0>, cudaFuncAttributeMaxDynamicSharedMemorySize, GEMM_SMEM);
    cudaFuncSetAttribute(tc_gemm<1>, cudaFuncAttributeMaxDynamicSharedMemorySize, GEMM_SMEM);

    rope_table_kernel<<<Tc, 32>>>(pcos, psin);

    // splits
    split_kernel<<<(Mc * Ec / 4 + 255) / 256, 256>>>(x, xhi, xlo, Mc * Ec / 4);
    split_kernel<<<(int)(WSZ / 4 + 255) / 256, 256>>>(Wq,   whi + 0 * WSZ, wlo + 0 * WSZ, (int)(WSZ / 4));
    split_kernel<<<(int)(WSZ / 4 + 255) / 256, 256>>>(Wk,   whi + 1 * WSZ, wlo + 1 * WSZ, (int)(WSZ / 4));
    split_kernel<<<(int)(WSZ / 4 + 255) / 256, 256>>>(Wv,   whi + 2 * WSZ, wlo + 2 * WSZ, (int)(WSZ / 4));
    split_kernel<<<(int)(WSZ / 4 + 255) / 256, 256>>>(Wout, whi + 3 * WSZ, wlo + 3 * WSZ, (int)(WSZ / 4));

    dim3 gg(Ec / 128, Mc / 128);   // (8, 128)
    tc_gemm<1><<<gg, 256, GEMM_SMEM>>>(xhi, xlo, whi + 0 * WSZ, wlo + 0 * WSZ, pq, pcos, psin);
    tc_gemm<1><<<gg, 256, GEMM_SMEM>>>(xhi, xlo, whi + 1 * WSZ, wlo + 1 * WSZ, pk, pcos, psin);
    tc_gemm<0><<<gg, 256, GEMM_SMEM>>>(xhi, xlo, whi + 2 * WSZ, wlo + 2 * WSZ, pv, pcos, psin);

    zero_kernel<<<(Bc * Hc * Sc * Dc + 255) / 256, 256>>>(pslot, Bc * Hc * Sc * Dc);

    write_kernel<<<dim3(8, Hc, Bc), 256>>>(pk, pv, slot_keys, pslot);
    read_kernel<<<dim3(8, Hc, Bc), 256>>>(pq, pslot, pro);

    split_kernel<<<(Mc * Ec / 4 + 255) / 256, 256>>>(pro, rohi, rolo, Mc * Ec / 4);
    tc_gemm<0><<<gg, 256, GEMM_SMEM>>>(rohi, rolo, whi + 3 * WSZ, wlo + 3 * WSZ, out, pcos, psin);
}